// round 8
// baseline (speedup 1.0000x reference)
#include <cuda_runtime.h>
#include <math.h>
#include <stdint.h>

// =====================================================================
// PtychoAD forward: 32 batches x 4 probe modes, 8-slice multislice,
// 256x256 complex fields, custom warp FFT (no cuFFT — allocation rules).
//
// DIF forward leaves spectrum digit-permuted: perm(8l+p)=8*brev5(l)+brev3(p)
// at lane l, reg p. psi is stored with x digit-permuted, H pre-permuted in
// both axes, inverse FFTs are DIT networks (permuted in, natural out).
// No reorder exchanges anywhere. All twiddles come from lane-indexed
// [factor][lane] tables -> every twiddle load is one coalesced LDG.64.
//
// g_psi[(b*4+m)*65536 + y*256 + x']  (y natural, x' = permuted kx/x)
// Launches (17, all graph-capturable):
//   k_init  : twiddle tables (double precision) + permuted-transposed H
//   k_pass0 : probe bilinear translate * obj[z=0] -> rowFFT(DIF)
//   7x { k_passC: colFFT(DIF) * Hperm * colIFFT(DIT)   [smem transpose]
//        k_passR: rowIFFT(DIT) * obj[z] * rowFFT(DIF)  [no reorder smem] }
//   k_passC2: colFFT(DIF) + |.|^2 over 4 modes -> dp (de-permuted store)
// =====================================================================

#define WFULL 0xffffffffu

static __device__ __forceinline__ float2 cadd(float2 a, float2 b){ return make_float2(a.x+b.x, a.y+b.y); }
static __device__ __forceinline__ float2 csub(float2 a, float2 b){ return make_float2(a.x-b.x, a.y-b.y); }
static __device__ __forceinline__ float2 cmul(float2 a, float2 b){ return make_float2(a.x*b.x - a.y*b.y, a.x*b.y + a.y*b.x); }

__device__ __align__(16)  float2 g_psi[32*4*256*256]; // 64 MB psi scratch
__device__ __align__(16)  float2 g_Ht[256*256];       // Ht[x'*256+t] = H[perm(t)][perm(x')]
// lane-indexed twiddle tables (rows of 32 float2 = 256B, line-aligned)
__device__ __align__(256) float2 g_twF [7][32];  // fwd inter-factor: W256^{lane*BR3[p]}
__device__ __align__(256) float2 g_twFi[7][32];  // conj of g_twF
__device__ __align__(256) float2 g_twS [4][32];  // fwd stage s: W256^{(lane&(m-1))*step}, m=16>>s, step=8<<s
__device__ __align__(256) float2 g_twSi[4][32];  // inv stage si: conj, m=1<<si, step=128>>si

// column-tile swizzle (float2 units): conflict-free for y=lane+32j
// load/store patterns and the linear float4 gmem staging.
static __device__ __forceinline__ int swzC(int y, int c){
  return (y<<4) | ((c ^ (y>>4) ^ y) & 15);
}

// ---------------------------------------------------------------------
// 8-point DIF in registers (natural in, reg p = X8[brev3(p)] out)
// ---------------------------------------------------------------------
static __device__ __forceinline__ void dif8(float2 (&v)[8]){
  const float C = 0.70710678118654752440f;
  float2 u,w,d;
  // stage m=4, twiddles W8^p on (a-b)
  u=v[0]; w=v[4]; v[0]=cadd(u,w); v[4]=csub(u,w);
  u=v[1]; w=v[5]; v[1]=cadd(u,w); d=csub(u,w);
  v[5] = make_float2(C*(d.x+d.y),  C*(d.y-d.x));          // *(1-i)/sqrt2
  u=v[2]; w=v[6]; v[2]=cadd(u,w); d=csub(u,w);
  v[6] = make_float2(d.y, -d.x);                          // *(-i)
  u=v[3]; w=v[7]; v[3]=cadd(u,w); d=csub(u,w);
  v[7] = make_float2(C*(d.y-d.x), -C*(d.x+d.y));          // *(-1-i)/sqrt2
  // stage m=2, twiddle W4^1=-i on odd pairs
  u=v[0]; w=v[2]; v[0]=cadd(u,w); v[2]=csub(u,w);
  u=v[1]; w=v[3]; v[1]=cadd(u,w); d=csub(u,w); v[3]=make_float2(d.y,-d.x);
  u=v[4]; w=v[6]; v[4]=cadd(u,w); v[6]=csub(u,w);
  u=v[5]; w=v[7]; v[5]=cadd(u,w); d=csub(u,w); v[7]=make_float2(d.y,-d.x);
  // stage m=1
  u=v[0]; w=v[1]; v[0]=cadd(u,w); v[1]=csub(u,w);
  u=v[2]; w=v[3]; v[2]=cadd(u,w); v[3]=csub(u,w);
  u=v[4]; w=v[5]; v[4]=cadd(u,w); v[5]=csub(u,w);
  u=v[6]; w=v[7]; v[6]=cadd(u,w); v[7]=csub(u,w);
}

// ---------------------------------------------------------------------
// 8-point DIT inverse in registers: exact inverse network of dif8 with
// conjugate twiddles (input reg p = Y8[brev3(p)], natural out, no scale)
// ---------------------------------------------------------------------
static __device__ __forceinline__ void dit8inv(float2 (&v)[8]){
  const float C = 0.70710678118654752440f;
  float2 a,b,tb;
  // m=1
  a=v[0]; b=v[1]; v[0]=cadd(a,b); v[1]=csub(a,b);
  a=v[2]; b=v[3]; v[2]=cadd(a,b); v[3]=csub(a,b);
  a=v[4]; b=v[5]; v[4]=cadd(a,b); v[5]=csub(a,b);
  a=v[6]; b=v[7]; v[6]=cadd(a,b); v[7]=csub(a,b);
  // m=2: conj twiddles {1, +i}
  a=v[0]; b=v[2]; v[0]=cadd(a,b); v[2]=csub(a,b);
  a=v[1]; b=v[3]; tb=make_float2(-b.y,b.x); v[1]=cadd(a,tb); v[3]=csub(a,tb);
  a=v[4]; b=v[6]; v[4]=cadd(a,b); v[6]=csub(a,b);
  a=v[5]; b=v[7]; tb=make_float2(-b.y,b.x); v[5]=cadd(a,tb); v[7]=csub(a,tb);
  // m=4: conj twiddles {1, (1+i)/s2, +i, (-1+i)/s2}
  a=v[0]; b=v[4]; v[0]=cadd(a,b); v[4]=csub(a,b);
  a=v[1]; b=v[5]; tb=make_float2(C*(b.x-b.y), C*(b.x+b.y));
  v[1]=cadd(a,tb); v[5]=csub(a,tb);
  a=v[2]; b=v[6]; tb=make_float2(-b.y,b.x); v[2]=cadd(a,tb); v[6]=csub(a,tb);
  a=v[3]; b=v[7]; tb=make_float2(-C*(b.x+b.y), C*(b.x-b.y));
  v[3]=cadd(a,tb); v[7]=csub(a,tb);
}

// ---------------------------------------------------------------------
// Forward warp 256-pt DIF. In: v[j]=x[lane+32j]. Out: lane l, reg p
// holds X[8*brev5(l)+brev3(p)]  (== gmem position x'=8l+p).
// ---------------------------------------------------------------------
static __device__ __forceinline__ void dif256(float2 (&v)[8], int lane){
  dif8(v);
  #pragma unroll
  for(int p=1;p<8;p++)
    v[p] = cmul(v[p], g_twF[p-1][lane]);   // coalesced 256B row
  #pragma unroll
  for(int s=0;s<4;s++){
    const int m = 16>>s;
    float2 t = g_twS[s][lane];             // coalesced 256B row
    bool up = ((lane & m)==0);
    #pragma unroll
    for(int p=0;p<8;p++){
      float ox = __shfl_xor_sync(WFULL, v[p].x, m);
      float oy = __shfl_xor_sync(WFULL, v[p].y, m);
      float2 o = make_float2(ox, oy);
      v[p] = up ? cadd(v[p], o) : cmul(csub(o, v[p]), t);
    }
  }
  { // m=1, twiddle = 1
    bool up = ((lane & 1)==0);
    #pragma unroll
    for(int p=0;p<8;p++){
      float ox = __shfl_xor_sync(WFULL, v[p].x, 1);
      float oy = __shfl_xor_sync(WFULL, v[p].y, 1);
      float2 o = make_float2(ox, oy);
      v[p] = up ? cadd(v[p], o) : csub(o, v[p]);
    }
  }
}

// ---------------------------------------------------------------------
// Inverse warp 256-pt DIT (exact inverse of dif256, conj twiddles,
// scaled 1/256). In: lane l, reg p = Y[8*brev5(l)+brev3(p)].
// Out: v[j] = y[lane+32j] (natural).
// ---------------------------------------------------------------------
static __device__ __forceinline__ void dit256inv(float2 (&v)[8], int lane){
  { // m=1, twiddle = 1
    bool up = ((lane & 1)==0);
    #pragma unroll
    for(int p=0;p<8;p++){
      float ox = __shfl_xor_sync(WFULL, v[p].x, 1);
      float oy = __shfl_xor_sync(WFULL, v[p].y, 1);
      float2 o = make_float2(ox, oy);
      v[p] = up ? cadd(v[p], o) : csub(o, v[p]);
    }
  }
  #pragma unroll
  for(int s=1;s<5;s++){
    const int m = 1<<s;
    float2 t = g_twSi[s-1][lane];          // pre-conjugated, coalesced
    bool up = ((lane & m)==0);
    #pragma unroll
    for(int p=0;p<8;p++){
      float ox = __shfl_xor_sync(WFULL, v[p].x, m);
      float oy = __shfl_xor_sync(WFULL, v[p].y, m);
      float2 o = make_float2(ox, oy);
      float2 src = up ? o : v[p];
      float2 tm = cmul(t, src);
      v[p] = up ? cadd(v[p], tm) : csub(o, tm);
    }
  }
  #pragma unroll
  for(int p=1;p<8;p++)
    v[p] = cmul(v[p], g_twFi[p-1][lane]);  // pre-conjugated, coalesced
  dit8inv(v);
  const float sc = 1.0f/256.0f;
  #pragma unroll
  for(int p=0;p<8;p++){ v[p].x*=sc; v[p].y*=sc; }
}

// digit permutation (involution): perm(8l+p) = 8*brev5(l)+brev3(p)
static __device__ __forceinline__ int perm8(int i){
  return 8*(__brev(i>>3)>>27) + (__brev(i&7)>>29);
}

// store registers (DIF output order) to a row at float2 index 8*lane+p
static __device__ __forceinline__ void store_perm_row(float2* row, const float2 (&v)[8], int lane){
  float4* out4 = (float4*)row;
  #pragma unroll
  for(int t=0;t<4;t++)
    out4[4*lane + t] = make_float4(v[2*t].x, v[2*t].y, v[2*t+1].x, v[2*t+1].y);
}
// load a permuted row into DIT input order
static __device__ __forceinline__ void load_perm_row(const float2* row, float2 (&v)[8], int lane){
  const float4* in4 = (const float4*)row;
  #pragma unroll
  for(int t=0;t<4;t++){
    float4 q = in4[4*lane + t];
    v[2*t]   = make_float2(q.x, q.y);
    v[2*t+1] = make_float2(q.z, q.w);
  }
}

// ---------------------------------------------------------------------
// Init: twiddle tables + permuted-transposed H
// Ht[x'*256 + t] = H[perm(t)][perm(x')]
// ---------------------------------------------------------------------
__global__ void k_init(const float* __restrict__ Hr, const float* __restrict__ Hi){
  int b = blockIdx.x, t = threadIdx.x;
  g_Ht[b*256 + t] = make_float2(Hr[perm8(t)*256 + perm8(b)], Hi[perm8(t)*256 + perm8(b)]);
  if(b == 0){
    const double PI2 = 6.2831853071795864769252867665590;
    int lane = t & 31, r = t >> 5;     // r: 0..7
    if(r < 7){
      const int BR3[8]={0,4,2,6,1,5,3,7};
      int k2 = BR3[r+1];
      double a = -PI2 * (double)((lane*k2) & 255) / 256.0;
      float cx = (float)cos(a), sx = (float)sin(a);
      g_twF [r][lane] = make_float2(cx,  sx);
      g_twFi[r][lane] = make_float2(cx, -sx);
    } else {
      #pragma unroll
      for(int s=0;s<4;s++){            // forward stage s: m=16>>s, step=8<<s
        int m = 16>>s, step = 8<<s;
        double a = -PI2 * (double)((lane & (m-1)) * step) / 256.0;
        g_twS[s][lane] = make_float2((float)cos(a), (float)sin(a));
      }
      #pragma unroll
      for(int si=1;si<5;si++){         // inverse stage si: m=1<<si, step=128>>si, conj
        int m = 1<<si, step = 128>>si;
        double a = PI2 * (double)((lane & (m-1)) * step) / 256.0;
        g_twSi[si-1][lane] = make_float2((float)cos(a), (float)sin(a));
      }
    }
  }
}

// ---------------------------------------------------------------------
// Pass 0: psi = probe_translated * obj[z=0] -> rowFFT, permuted store.
// grid (16 tiles, 4 modes, 32 batches), 512 thr: warp w -> row tile*16+w
// ---------------------------------------------------------------------
__global__ __launch_bounds__(512) void k_pass0(
    const float* __restrict__ obj, const float* __restrict__ probe,
    const float* __restrict__ shifts, const int* __restrict__ crop,
    const int* __restrict__ indices)
{
  int tile = blockIdx.x, m = blockIdx.y, b = blockIdx.z;
  int w = threadIdx.x >> 5, lane = threadIdx.x & 31;
  int idx = indices[b];
  int py = crop[2*idx], px = crop[2*idx+1];
  float tH = shifts[2*idx], tW = shifts[2*idx+1];
  int y = tile*16 + w;

  float ys = (float)y - tH;
  float y0f = floorf(ys); float wy = ys - y0f; int y0 = (int)y0f;

  const float2* probe2 = (const float2*)probe;   // [4][256][256]
  const float2* obj2   = (const float2*)obj;     // [8][1024][1024]

  float2 v[8];
  #pragma unroll
  for(int j=0;j<8;j++){
    int x = lane + 32*j;
    float xs = (float)x - tW;
    float x0f = floorf(xs); float wx = xs - x0f; int x0 = (int)x0f;
    float A = 0.f, P = 0.f;
    #pragma unroll
    for(int dy=0;dy<2;dy++){
      int yi = y0 + dy; bool vy = (yi>=0) && (yi<256);
      int yc = vy ? yi : 0;
      float wyv = dy ? wy : (1.f - wy);
      #pragma unroll
      for(int dx=0;dx<2;dx++){
        int xi = x0 + dx; bool vx = (xi>=0) && (xi<256);
        int xc = vx ? xi : 0;
        float wt = wyv * (dx ? wx : (1.f - wx));
        float2 tap = probe2[(m*256 + yc)*256 + xc];
        if(!(vy && vx)){ tap.x = 0.f; tap.y = 0.f; }
        A += wt * tap.x; P += wt * tap.y;
      }
    }
    float sp, cp; __sincosf(P, &sp, &cp);
    float2 pc = make_float2(A*cp, A*sp);
    float2 og = obj2[(size_t)(py+y)*1024 + (px+x)];   // z = 0
    float so, co; __sincosf(og.y, &so, &co);
    v[j] = cmul(pc, make_float2(og.x*co, og.x*so));
  }
  dif256(v, lane);
  store_perm_row(g_psi + ((size_t)(b*4 + m)*256 + y)*256, v, lane);
}

// ---------------------------------------------------------------------
// Pass C: colFFT(DIF) -> * Hperm (register order) -> colIFFT(DIT).
// In place. grid (16 col-tiles, 128 fields), 512 thr, warp w: column w.
// ---------------------------------------------------------------------
__global__ __launch_bounds__(512) void k_passC(){
  __shared__ float2 tile[256*16];   // swizzled, 32 KB
  int tx = blockIdx.x, f = blockIdx.y;
  int tid = threadIdx.x, w = tid>>5, lane = tid&31;
  int cbase = tx*16;
  float2* base = g_psi + (size_t)f*65536;
  const float4* base4 = (const float4*)(base + cbase);

  // stage in: float4 gmem reads -> two swizzled float2 smem writes
  #pragma unroll
  for(int k=0;k<4;k++){
    int e = k*512 + tid; int y = e>>3, c4 = e&7;
    float4 q = base4[y*128 + c4];
    tile[swzC(y, 2*c4  )] = make_float2(q.x, q.y);
    tile[swzC(y, 2*c4+1)] = make_float2(q.z, q.w);
  }
  __syncthreads();

  float2 v[8];
  #pragma unroll
  for(int j=0;j<8;j++) v[j] = tile[swzC(lane + 32*j, w)];
  dif256(v, lane);
  // H multiply directly in permuted register order (coalesced 64B/lane)
  {
    const float4* Hc = (const float4*)(g_Ht + (size_t)(cbase + w)*256);
    #pragma unroll
    for(int t=0;t<4;t++){
      float4 h = Hc[4*lane + t];
      v[2*t]   = cmul(v[2*t],   make_float2(h.x, h.y));
      v[2*t+1] = cmul(v[2*t+1], make_float2(h.z, h.w));
    }
  }
  dit256inv(v, lane);   // natural y out
  #pragma unroll
  for(int j=0;j<8;j++) tile[swzC(lane + 32*j, w)] = v[j];
  __syncthreads();

  // stage out
  float4* obase4 = (float4*)(base + cbase);
  #pragma unroll
  for(int k=0;k<4;k++){
    int e = k*512 + tid; int y = e>>3, c4 = e&7;
    float2 a = tile[swzC(y, 2*c4  )];
    float2 c = tile[swzC(y, 2*c4+1)];
    obase4[y*128 + c4] = make_float4(a.x, a.y, c.x, c.y);
  }
}

// ---------------------------------------------------------------------
// Pass R: rowIFFT(DIT) * obj[z] * rowFFT(DIF). In place, no reorder.
// One block per (row-tile, batch); loops the 4 probe modes sharing the
// object rows staged (converted to complex) in smem.
// grid (16, 32), 512 thr, warp w -> row tile*16+w.
// ---------------------------------------------------------------------
__global__ __launch_bounds__(512) void k_passR(
    const float* __restrict__ obj, const int* __restrict__ crop,
    const int* __restrict__ indices, int z)
{
  __shared__ float2 buf[16*256];   // obj rows as complex, 32 KB
  int tile = blockIdx.x, b = blockIdx.y;
  int tid = threadIdx.x, w = tid>>5, lane = tid&31;
  int idx = indices[b];
  int py = crop[2*idx], px = crop[2*idx+1];

  const float2* obj2 = (const float2*)obj;
  #pragma unroll
  for(int k=0;k<8;k++){
    int e = k*512 + tid; int r = e>>8, x = e&255;
    float2 og = obj2[((size_t)z*1024 + py + tile*16 + r)*1024 + px + x];
    float s, c; __sincosf(og.y, &s, &c);
    buf[r*256 + x] = make_float2(og.x*c, og.x*s);
  }
  __syncthreads();

  int y = tile*16 + w;
  #pragma unroll 1
  for(int m=0;m<4;m++){
    float2* row = g_psi + (((size_t)(b*4 + m)*256) + y)*256;
    float2 v[8];
    load_perm_row(row, v, lane);
    dit256inv(v, lane);           // natural x
    #pragma unroll
    for(int j=0;j<8;j++) v[j] = cmul(v[j], buf[w*256 + lane + 32*j]);
    dif256(v, lane);
    store_perm_row(row, v, lane);
  }
}

// ---------------------------------------------------------------------
// Pass C2: final colFFT(DIF) + |.|^2 over 4 modes -> dp, de-permuted kx.
// grid (16 col-tiles, 32 batches), 512 thr.
// ---------------------------------------------------------------------
__global__ __launch_bounds__(512) void k_passC2(float* __restrict__ dp){
  __shared__ float2 tile[256*16];
  int tx = blockIdx.x, b = blockIdx.y;
  int tid = threadIdx.x, w = tid>>5, lane = tid&31;
  int cbase = tx*16;
  int rl = __brev(lane) >> 27;
  const int BR3[8]={0,4,2,6,1,5,3,7};

  float acc[8];
  #pragma unroll
  for(int p=0;p<8;p++) acc[p]=0.f;

  for(int m=0;m<4;m++){
    const float4* base4 = (const float4*)(g_psi + (size_t)(b*4 + m)*65536 + cbase);
    __syncthreads();
    #pragma unroll
    for(int k=0;k<4;k++){
      int e = k*512 + tid; int y = e>>3, c4 = e&7;
      float4 q = base4[y*128 + c4];
      tile[swzC(y, 2*c4  )] = make_float2(q.x, q.y);
      tile[swzC(y, 2*c4+1)] = make_float2(q.z, q.w);
    }
    __syncthreads();
    float2 v[8];
    #pragma unroll
    for(int j=0;j<8;j++) v[j] = tile[swzC(lane + 32*j, w)];
    dif256(v, lane);
    #pragma unroll
    for(int p=0;p<8;p++) acc[p] += v[p].x*v[p].x + v[p].y*v[p].y;
  }
  __syncthreads();
  // store |.|^2 at TRUE ky with XOR-swizzled float layout [256][16]
  float* ft = (float*)tile;
  #pragma unroll
  for(int p=0;p<8;p++){
    int ky = 8*rl + BR3[p];
    ft[ky*16 + (w ^ ((ky>>4)&15))] = acc[p];
  }
  __syncthreads();
  #pragma unroll
  for(int k=0;k<8;k++){
    int e = k*512 + tid; int ky = e>>4, c = e&15;
    float val = ft[ky*16 + (c ^ ((ky>>4)&15))];
    int kx = perm8(cbase + c);    // de-permute column
    dp[((size_t)b*256 + ky)*256 + kx] = val;
  }
}

// ---------------------------------------------------------------------
extern "C" void kernel_launch(void* const* d_in, const int* in_sizes, int n_in,
                              void* d_out, int out_size)
{
  (void)in_sizes; (void)n_in; (void)out_size;
  const float* obj    = (const float*)d_in[0];   // (1,8,1024,1024,2) f32
  const float* probe  = (const float*)d_in[1];   // (4,256,256,2) f32
  const float* shifts = (const float*)d_in[2];   // (1024,2) f32
  const int*   crop   = (const int*)  d_in[3];   // (1024,2) i32
  const float* Hr     = (const float*)d_in[4];   // (256,256) f32
  const float* Hi     = (const float*)d_in[5];   // (256,256) f32
  const int*   idx    = (const int*)  d_in[6];   // (32,) i32
  float* dp = (float*)d_out;                     // (32,256,256) f32

  k_init<<<256, 256>>>(Hr, Hi);
  k_pass0<<<dim3(16,4,32), 512>>>(obj, probe, shifts, crop, idx);
  for(int z=1; z<8; z++){
    k_passC<<<dim3(16,128), 512>>>();
    k_passR<<<dim3(16,32), 512>>>(obj, crop, idx, z);
  }
  k_passC2<<<dim3(16,32), 512>>>(dp);
}